// round 1
// baseline (speedup 1.0000x reference)
#include <cuda_runtime.h>
#include <cuda_bf16.h>

// Problem constants: im1, im2 are [16, 3, 512, 512] float32.
#define NUM_BINS   256
#define BATCH      16
#define PER_BATCH  (3 * 512 * 512)          // 786432 elements per batch item
#define VEC_PER_BATCH (PER_BATCH / 4)       // 196608 float4 per batch item
#define BPB        32                       // blocks per batch item
#define VEC_PER_BLOCK (VEC_PER_BATCH / BPB) // 6144 float4 per block
#define THREADS    256
#define REPLICAS   2                        // smem histogram replicas (warp parity)

// Global scratch: per-batch histograms for both images.
// Layout: g_hist[b*512 + bin]        = im1 histogram of batch b
//         g_hist[b*512 + 256 + bin]  = im2 histogram of batch b
__device__ unsigned int g_hist[BATCH * 2 * NUM_BINS];

__device__ __forceinline__ int bin_of(float v) {
    // Exactly mirrors: floor((v*255) * (256/255)), clip [0, 255], fp32 math.
    float x = v * 255.0f;
    int i = (int)floorf(x * (256.0f / 255.0f));
    i = i < 0 ? 0 : i;
    i = i > 255 ? 255 : i;
    return i;
}

__global__ void zero_k() {
    int i = blockIdx.x * blockDim.x + threadIdx.x;
    if (i < BATCH * 2 * NUM_BINS) g_hist[i] = 0u;
}

__global__ __launch_bounds__(THREADS) void hist_k(const float4* __restrict__ im1,
                                                  const float4* __restrict__ im2) {
    // Replicated shared histograms: [replica][image][bin]
    __shared__ unsigned int sh[REPLICAS * 2 * NUM_BINS];

    const int b   = blockIdx.x / BPB;
    const int blk = blockIdx.x % BPB;
    const int tid = threadIdx.x;
    const int rep = (tid >> 5) & (REPLICAS - 1);  // warp parity picks replica
    unsigned int* h1 = &sh[rep * 2 * NUM_BINS];
    unsigned int* h2 = h1 + NUM_BINS;

    for (int i = tid; i < REPLICAS * 2 * NUM_BINS; i += THREADS) sh[i] = 0u;
    __syncthreads();

    const int base = b * VEC_PER_BATCH + blk * VEC_PER_BLOCK;
    #pragma unroll 4
    for (int i = tid; i < VEC_PER_BLOCK; i += THREADS) {
        float4 a = __ldg(&im1[base + i]);
        float4 c = __ldg(&im2[base + i]);
        atomicAdd(&h1[bin_of(a.x)], 1u);
        atomicAdd(&h1[bin_of(a.y)], 1u);
        atomicAdd(&h1[bin_of(a.z)], 1u);
        atomicAdd(&h1[bin_of(a.w)], 1u);
        atomicAdd(&h2[bin_of(c.x)], 1u);
        atomicAdd(&h2[bin_of(c.y)], 1u);
        atomicAdd(&h2[bin_of(c.z)], 1u);
        atomicAdd(&h2[bin_of(c.w)], 1u);
    }
    __syncthreads();

    // Merge replicas and flush to global histograms.
    unsigned int* g = &g_hist[b * 2 * NUM_BINS];
    for (int i = tid; i < 2 * NUM_BINS; i += THREADS) {
        unsigned int s = 0;
        #pragma unroll
        for (int r = 0; r < REPLICAS; r++) s += sh[r * 2 * NUM_BINS + i];
        if (s) atomicAdd(&g[i], s);
    }
}

__global__ __launch_bounds__(NUM_BINS) void emd_final(float* __restrict__ out) {
    __shared__ int s[NUM_BINS];
    __shared__ long long red[NUM_BINS];
    const int t = threadIdx.x;

    long long acc = 0;
    for (int b = 0; b < BATCH; b++) {
        // d[bin] = h1 - h2 (integer, exact). |cumsum(d)| summed == N * emd_b.
        int d = (int)g_hist[b * 2 * NUM_BINS + t] -
                (int)g_hist[b * 2 * NUM_BINS + NUM_BINS + t];
        s[t] = d;
        __syncthreads();
        // Hillis-Steele inclusive scan over 256 bins.
        #pragma unroll
        for (int off = 1; off < NUM_BINS; off <<= 1) {
            int v = (t >= off) ? s[t - off] : 0;
            __syncthreads();
            s[t] += v;
            __syncthreads();
        }
        long long c = (long long)s[t];
        acc += c < 0 ? -c : c;
        __syncthreads();
    }

    red[t] = acc;
    __syncthreads();
    #pragma unroll
    for (int off = NUM_BINS / 2; off > 0; off >>= 1) {
        if (t < off) red[t] += red[t + off];
        __syncthreads();
    }

    if (t == 0) {
        // total = sum_b emd_b / 256 / 3, where emd_b = acc_b / PER_BATCH
        double total = (double)red[0] / (double)PER_BATCH / (double)NUM_BINS / 3.0;
        out[0] = (float)total;
    }
}

extern "C" void kernel_launch(void* const* d_in, const int* in_sizes, int n_in,
                              void* d_out, int out_size) {
    const float4* im1 = (const float4*)d_in[0];
    const float4* im2 = (const float4*)d_in[1];
    float* out = (float*)d_out;

    zero_k<<<(BATCH * 2 * NUM_BINS + 255) / 256, 256>>>();
    hist_k<<<BATCH * BPB, THREADS>>>(im1, im2);
    emd_final<<<1, NUM_BINS>>>(out);
}

// round 2
// speedup vs baseline: 1.0856x; 1.0856x over previous
#include <cuda_runtime.h>
#include <cuda_bf16.h>

// Problem constants: im1, im2 are [16, 3, 512, 512] float32.
#define NUM_BINS   256
#define BATCH      16
#define PER_BATCH  (3 * 512 * 512)          // 786432 elements per batch item
#define VEC_PER_BATCH (PER_BATCH / 4)       // 196608 float4 per batch item
#define BPB        64                       // blocks per batch item
#define VEC_PER_BLOCK (VEC_PER_BATCH / BPB) // 3072 float4 per block
#define THREADS    256
#define REPLICAS   8                        // one smem histogram replica per warp

// Global scratch: per-batch histograms for both images.
// Layout: g_hist[b*512 + bin]        = im1 histogram of batch b
//         g_hist[b*512 + 256 + bin]  = im2 histogram of batch b
// Zero-initialized at module load; emd_final re-zeroes it after reading so
// every graph replay sees the same initial state (no zero_k launch needed).
__device__ unsigned int g_hist[BATCH * 2 * NUM_BINS];

__device__ __forceinline__ int bin_of(float v) {
    // Exactly mirrors reference: floor((v*255) * (256/255)), clip, fp32 math.
    float x = v * 255.0f;
    int i = (int)floorf(x * (256.0f / 255.0f));
    i = i < 0 ? 0 : i;
    i = i > 255 ? 255 : i;
    return i;
}

__global__ __launch_bounds__(THREADS) void hist_k(const float4* __restrict__ im1,
                                                  const float4* __restrict__ im2) {
    // Per-warp replicated shared histograms: [warp][image][bin]
    __shared__ unsigned int sh[REPLICAS * 2 * NUM_BINS];

    const int b   = blockIdx.x / BPB;
    const int blk = blockIdx.x % BPB;
    const int tid = threadIdx.x;
    const int rep = tid >> 5;               // warp id == replica id (8 warps)
    unsigned int* h1 = &sh[rep * 2 * NUM_BINS];
    unsigned int* h2 = h1 + NUM_BINS;

    #pragma unroll
    for (int i = tid; i < REPLICAS * 2 * NUM_BINS; i += THREADS) sh[i] = 0u;
    __syncthreads();

    const int base = b * VEC_PER_BATCH + blk * VEC_PER_BLOCK;
    #pragma unroll 4
    for (int i = tid; i < VEC_PER_BLOCK; i += THREADS) {
        float4 a = __ldg(&im1[base + i]);
        float4 c = __ldg(&im2[base + i]);
        atomicAdd(&h1[bin_of(a.x)], 1u);
        atomicAdd(&h1[bin_of(a.y)], 1u);
        atomicAdd(&h1[bin_of(a.z)], 1u);
        atomicAdd(&h1[bin_of(a.w)], 1u);
        atomicAdd(&h2[bin_of(c.x)], 1u);
        atomicAdd(&h2[bin_of(c.y)], 1u);
        atomicAdd(&h2[bin_of(c.z)], 1u);
        atomicAdd(&h2[bin_of(c.w)], 1u);
    }
    __syncthreads();

    // Merge warp replicas and flush to global histograms (RED, no return).
    unsigned int* g = &g_hist[b * 2 * NUM_BINS];
    for (int i = tid; i < 2 * NUM_BINS; i += THREADS) {
        unsigned int s = 0;
        #pragma unroll
        for (int r = 0; r < REPLICAS; r++) s += sh[r * 2 * NUM_BINS + i];
        atomicAdd(&g[i], s);
    }
}

__global__ __launch_bounds__(NUM_BINS) void emd_final(float* __restrict__ out) {
    __shared__ int s[NUM_BINS];
    __shared__ long long red[NUM_BINS];
    const int t = threadIdx.x;

    long long acc = 0;
    for (int b = 0; b < BATCH; b++) {
        // d[bin] = h1 - h2 (integer, exact). |cumsum(d)| summed == N * emd_b.
        int d = (int)g_hist[b * 2 * NUM_BINS + t] -
                (int)g_hist[b * 2 * NUM_BINS + NUM_BINS + t];
        s[t] = d;
        __syncthreads();
        // Hillis-Steele inclusive scan over 256 bins.
        #pragma unroll
        for (int off = 1; off < NUM_BINS; off <<= 1) {
            int v = (t >= off) ? s[t - off] : 0;
            __syncthreads();
            s[t] += v;
            __syncthreads();
        }
        long long c = (long long)s[t];
        acc += c < 0 ? -c : c;
        __syncthreads();
    }

    red[t] = acc;
    __syncthreads();
    #pragma unroll
    for (int off = NUM_BINS / 2; off > 0; off >>= 1) {
        if (t < off) red[t] += red[t + off];
        __syncthreads();
    }

    if (t == 0) {
        // total = sum_b emd_b / 256 / 3, where emd_b = acc_b / PER_BATCH
        double total = (double)red[0] / (double)PER_BATCH / (double)NUM_BINS / 3.0;
        out[0] = (float)total;
    }
    __syncthreads();

    // Restore the zero-invariant of g_hist for the next graph replay.
    #pragma unroll
    for (int i = t; i < BATCH * 2 * NUM_BINS; i += NUM_BINS) g_hist[i] = 0u;
}

extern "C" void kernel_launch(void* const* d_in, const int* in_sizes, int n_in,
                              void* d_out, int out_size) {
    const float4* im1 = (const float4*)d_in[0];
    const float4* im2 = (const float4*)d_in[1];
    float* out = (float*)d_out;

    hist_k<<<BATCH * BPB, THREADS>>>(im1, im2);
    emd_final<<<1, NUM_BINS>>>(out);
}

// round 3
// speedup vs baseline: 1.4273x; 1.3148x over previous
#include <cuda_runtime.h>
#include <cuda_bf16.h>

// Problem constants: im1, im2 are [16, 3, 512, 512] float32.
#define NUM_BINS   256
#define BATCH      16
#define PER_BATCH  (3 * 512 * 512)          // 786432 elements per batch item
#define VEC_PER_BATCH (PER_BATCH / 4)       // 196608 float4 per batch item
#define BPB        64                       // blocks per batch item
#define VEC_PER_BLOCK (VEC_PER_BATCH / BPB) // 3072 float4 per block
#define THREADS    256
#define REPLICAS   8                        // one smem histogram replica per warp
#define GRID       (BATCH * BPB)            // 1024 blocks

// Per-batch histograms for both images, accumulated via L2 atomics.
// g_hist[b*512 + bin] = im1 hist of batch b; +256 = im2 hist.
// Zero at module load; the finalizing block re-zeroes after consuming, so
// every graph replay sees identical initial state.
__device__ unsigned int g_hist[BATCH * 2 * NUM_BINS];
__device__ unsigned int g_done;

__device__ __forceinline__ int bin_of(float v) {
    // Exactly mirrors reference: floor((v*255) * (256/255)), clip, fp32 math.
    float x = v * 255.0f;
    int i = (int)floorf(x * (256.0f / 255.0f));
    i = i < 0 ? 0 : i;
    i = i > 255 ? 255 : i;
    return i;
}

__device__ __forceinline__ uint4 ldcg4(const unsigned int* p) {
    return __ldcg((const uint4*)p);
}

__global__ __launch_bounds__(THREADS) void fused_k(const float4* __restrict__ im1,
                                                   const float4* __restrict__ im2,
                                                   float* __restrict__ out) {
    // Per-warp replicated shared histograms: [warp][image][bin]
    __shared__ unsigned int sh[REPLICAS * 2 * NUM_BINS];
    __shared__ bool is_last;
    __shared__ long long warp_acc[REPLICAS];

    const int b    = blockIdx.x / BPB;
    const int blk  = blockIdx.x % BPB;
    const int tid  = threadIdx.x;
    const int wid  = tid >> 5;
    const int lane = tid & 31;
    unsigned int* h1 = &sh[wid * 2 * NUM_BINS];
    unsigned int* h2 = h1 + NUM_BINS;

    #pragma unroll
    for (int i = tid; i < REPLICAS * 2 * NUM_BINS; i += THREADS) sh[i] = 0u;
    __syncthreads();

    // ---- Phase 1: histogram this block's slice of both images ----
    const int base = b * VEC_PER_BATCH + blk * VEC_PER_BLOCK;
    #pragma unroll 4
    for (int i = tid; i < VEC_PER_BLOCK; i += THREADS) {
        float4 a = __ldg(&im1[base + i]);
        float4 c = __ldg(&im2[base + i]);
        atomicAdd(&h1[bin_of(a.x)], 1u);
        atomicAdd(&h1[bin_of(a.y)], 1u);
        atomicAdd(&h1[bin_of(a.z)], 1u);
        atomicAdd(&h1[bin_of(a.w)], 1u);
        atomicAdd(&h2[bin_of(c.x)], 1u);
        atomicAdd(&h2[bin_of(c.y)], 1u);
        atomicAdd(&h2[bin_of(c.z)], 1u);
        atomicAdd(&h2[bin_of(c.w)], 1u);
    }
    __syncthreads();

    // Merge warp replicas, flush to global histograms.
    unsigned int* g = &g_hist[b * 2 * NUM_BINS];
    for (int i = tid; i < 2 * NUM_BINS; i += THREADS) {
        unsigned int s = 0;
        #pragma unroll
        for (int r = 0; r < REPLICAS; r++) s += sh[r * 2 * NUM_BINS + i];
        atomicAdd(&g[i], s);
    }

    // ---- Last-block-done handoff ----
    __threadfence();
    __syncthreads();
    if (tid == 0) is_last = (atomicAdd(&g_done, 1u) == GRID - 1);
    __syncthreads();
    if (!is_last) return;

    // ---- Phase 2 (one block): EMD finalization, barrier-free scans ----
    // Warp w handles batches w and w+8. Lane holds 8 consecutive bins.
    long long acc = 0;
    #pragma unroll
    for (int bb = 0; bb < 2; bb++) {
        const int bat  = wid + bb * REPLICAS;
        const unsigned int* hb = &g_hist[bat * 2 * NUM_BINS];

        uint4 a0 = ldcg4(hb + lane * 8);
        uint4 a1 = ldcg4(hb + lane * 8 + 4);
        uint4 c0 = ldcg4(hb + NUM_BINS + lane * 8);
        uint4 c1 = ldcg4(hb + NUM_BINS + lane * 8 + 4);

        int d[8];
        d[0] = (int)a0.x - (int)c0.x;  d[1] = (int)a0.y - (int)c0.y;
        d[2] = (int)a0.z - (int)c0.z;  d[3] = (int)a0.w - (int)c0.w;
        d[4] = (int)a1.x - (int)c1.x;  d[5] = (int)a1.y - (int)c1.y;
        d[6] = (int)a1.z - (int)c1.z;  d[7] = (int)a1.w - (int)c1.w;

        // In-lane sequential inclusive prefix over 8 bins.
        #pragma unroll
        for (int j = 1; j < 8; j++) d[j] += d[j - 1];

        // Warp-wide exclusive scan of lane totals (5 shuffles).
        int inc = d[7];
        #pragma unroll
        for (int off = 1; off < 32; off <<= 1) {
            int v = __shfl_up_sync(0xffffffffu, inc, off);
            if (lane >= off) inc += v;
        }
        const int ex = inc - d[7];

        #pragma unroll
        for (int j = 0; j < 8; j++) {
            int c = d[j] + ex;                 // integer cumsum = N * normalized
            acc += (c < 0) ? (long long)(-c) : (long long)c;
        }
    }

    // Reduce across lanes, then across the 8 warps.
    #pragma unroll
    for (int off = 16; off > 0; off >>= 1)
        acc += __shfl_down_sync(0xffffffffu, acc, off);
    if (lane == 0) warp_acc[wid] = acc;
    __syncthreads();

    if (tid == 0) {
        long long total_i = 0;
        #pragma unroll
        for (int w = 0; w < REPLICAS; w++) total_i += warp_acc[w];
        // total = (sum_b acc_b / N) / 256 / 3
        double total = (double)total_i / (double)PER_BATCH / (double)NUM_BINS / 3.0;
        out[0] = (float)total;
    }
    __syncthreads();

    // Restore zero-invariant for next graph replay.
    for (int i = tid; i < BATCH * 2 * NUM_BINS; i += THREADS) g_hist[i] = 0u;
    if (tid == 0) g_done = 0u;
}

extern "C" void kernel_launch(void* const* d_in, const int* in_sizes, int n_in,
                              void* d_out, int out_size) {
    const float4* im1 = (const float4*)d_in[0];
    const float4* im2 = (const float4*)d_in[1];
    float* out = (float*)d_out;

    fused_k<<<GRID, THREADS>>>(im1, im2, out);
}